// round 4
// baseline (speedup 1.0000x reference)
#include <cuda_runtime.h>
#include <cstddef>

// Problem constants
#define BB   8
#define CC   62
#define CIN  64
#define GG   26
#define G3   17576          // 26^3
#define G2   676            // 26^2
#define NPT  32768
#define HH   1024
#define YSZ  (BB*3*NPT)     // 786432, offset of reg block in output

typedef unsigned long long u64;

// ---------------- scratch (no allocations allowed) ----------------
__device__ float g_csum[BB * G3];
__device__ int   g_counts[BB * G3];
__device__ int   g_sorted[BB * NPT];

// ---------------- packed f32x2 FMA ----------------
__device__ __forceinline__ u64 fma2(u64 a, u64 b, u64 c) {
    u64 d;
    asm("fma.rn.f32x2 %0, %1, %2, %3;" : "=l"(d) : "l"(a), "l"(b), "l"(c));
    return d;
}

// ---------------- kernel 1: XLA:CPU ReduceWindowRewriter-exact cumsum + count zeroing ----------------
// jnp.cumsum on CPU lowers to reduce_window; XLA:CPU's ReduceWindowRewriter
// (base_length=16) rewrites it into a blocked hierarchical scan:
//   - contiguous 16-element blocks, serial scan within block
//   - block totals scanned recursively (17576 -> 1099 -> 69 -> 5, then naive serial)
//   - element = (in-block serial prefix) + (prev-blocks prefix) (block0 adds +0.0f)
#define NB1 1099   // ceil(17576/16)
#define NB2 69     // ceil(1099/16)
#define NB3 5      // ceil(69/16), <= 16 -> naive serial

__global__ __launch_bounds__(1024) void k_cumsum_rw(const float* __restrict__ dens) {
    __shared__ float T1[NB1];
    __shared__ float T2[NB2];
    __shared__ float T3[NB3];
    const int b = blockIdx.x;
    const int tid = threadIdx.x;
    const float* d = dens + (size_t)b * G3;

    // fused: zero this batch's histogram (int4-vectorized, 17576 % 4 == 0)
    {
        int4* cz = reinterpret_cast<int4*>(g_counts + b * G3);
        const int n4 = G3 / 4;  // 4394
        for (int i = tid; i < n4; i += 1024) cz[i] = make_int4(0, 0, 0, 0);
    }

    // level-0 block sums (serial within block, left to right)
    for (int j = tid; j < NB1; j += 1024) {
        const int s0 = j * 16;
        const int e0 = min(s0 + 16, G3);
        float s = 0.f;
        for (int i = s0; i < e0; ++i) s += d[i];
        T1[j] = s;
    }
    __syncthreads();
    // level-1 block sums
    if (tid < NB2) {
        const int s1 = tid * 16;
        const int e1 = min(s1 + 16, NB1);
        float s = 0.f;
        for (int i = s1; i < e1; ++i) s += T1[i];
        T2[tid] = s;
    }
    __syncthreads();
    // level-2 block sums, cs3 (naive serial), cs2 (in place over T2)
    if (tid == 0) {
        for (int j = 0; j < NB3; ++j) {
            const int s2 = j * 16;
            const int e2 = min(s2 + 16, NB2);
            float s = 0.f;
            for (int i = s2; i < e2; ++i) s += T2[i];
            T3[j] = s;
        }
        float s = 0.f;
        for (int j = 0; j < NB3; ++j) { s += T3[j]; T3[j] = s; }
        for (int j2 = 0; j2 < NB3; ++j2) {
            const float P = (j2 > 0) ? T3[j2 - 1] : 0.0f;
            float sr = 0.f;
            const int s2 = j2 * 16, e2 = min(j2 * 16 + 16, NB2);
            for (int i = s2; i < e2; ++i) {
                sr += T2[i];
                T2[i] = sr + P;
            }
        }
    }
    __syncthreads();
    // cs1 in place over T1 (one thread per level-1 chunk)
    if (tid < NB2) {
        const float P = (tid > 0) ? T2[tid - 1] : 0.0f;
        float sr = 0.f;
        const int s1 = tid * 16, e1 = min(tid * 16 + 16, NB1);
        for (int i = s1; i < e1; ++i) {
            sr += T1[i];
            T1[i] = sr + P;
        }
    }
    __syncthreads();
    // cs0 -> g_csum (one thread per level-0 chunk)
    float* cs = g_csum + (size_t)b * G3;
    for (int j = tid; j < NB1; j += 1024) {
        const float P = (j > 0) ? T1[j - 1] : 0.0f;
        float sr = 0.f;
        const int s0 = j * 16, e0 = min(j * 16 + 16, G3);
        for (int i = s0; i < e0; ++i) {
            sr += d[i];
            cs[i] = sr + P;
        }
    }
}

// ---------------- kernel 2: sample -> histogram ----------------
__global__ void k_sample(const float* __restrict__ u) {
    int g = blockIdx.x * blockDim.x + threadIdx.x;
    if (g >= BB * NPT) return;
    int b = g >> 15;  // /32768
    const float* cs = g_csum + (size_t)b * G3;
    float total = cs[G3 - 1];
    float t = u[g] * total;
    // searchsorted side='right': first index with cs[idx] > t
    int lo = 0, hi = G3;
    while (lo < hi) {
        int mid = (lo + hi) >> 1;
        if (cs[mid] <= t) lo = mid + 1; else hi = mid;
    }
    int idx = lo;
    if (idx > G3 - 1) idx = G3 - 1;
    atomicAdd(&g_counts[b * G3 + idx], 1);
}

// ---------------- kernel 3: single-pass counting-sort emit ----------------
// Each thread owns 18 contiguous bins (1024*18 >= 17576). Register prefix +
// one 2-level block scan, then direct run-length emit. 3 syncs total.
#define BINS_PT 18
__global__ __launch_bounds__(1024) void k_scanfill() {
    const int b = blockIdx.x;
    const int* cnt = g_counts + b * G3;
    int* srt = g_sorted + b * NPT;

    __shared__ int wsum[32];
    const int tid = threadIdx.x;
    const int lane = tid & 31, wid = tid >> 5;
    const int base = tid * BINS_PT;

    int c[BINS_PT];
    int pre[BINS_PT];
    int s = 0;
    #pragma unroll
    for (int r = 0; r < BINS_PT; ++r) {
        const int i = base + r;
        c[r] = (i < G3) ? cnt[i] : 0;
        pre[r] = s;
        s += c[r];
    }
    // block exclusive scan of per-thread totals
    int x = s;
    #pragma unroll
    for (int d = 1; d < 32; d <<= 1) {
        int y = __shfl_up_sync(0xffffffffu, x, d);
        if (lane >= d) x += y;
    }
    if (lane == 31) wsum[wid] = x;
    __syncthreads();
    if (wid == 0) {
        int t = wsum[lane];
        #pragma unroll
        for (int d = 1; d < 32; d <<= 1) {
            int y = __shfl_up_sync(0xffffffffu, t, d);
            if (lane >= d) t += y;
        }
        wsum[lane] = t;
    }
    __syncthreads();
    const int excl = (x - s) + (wid ? wsum[wid - 1] : 0);

    // emit: bin i repeated c[r] times
    #pragma unroll
    for (int r = 0; r < BINS_PT; ++r) {
        const int i = base + r;
        const int o = excl + pre[r];
        for (int k = 0; k < c[r]; ++k) srt[o + k] = i;
    }
}

// ---------------- kernel 4: fused gather + MLP + epilogue ----------------
// Block: 256 threads, 128 points, 16 passes of 64 h-rows.
// Thread tile: 8 h (rowt + 8*i) x 4 points (col + 32*j), f32x2 packed over k-pairs.
// W1 tiles double-buffered: LDG for pass+1 issued before pass compute, 1 sync/pass.
#define PITCH 68
#define WBUF  (64 * PITCH)
#define SMEM_FLOATS (2*WBUF + 128*PITCH + 1024 + 3072 + 3072)
#define SMEM_BYTES  (SMEM_FLOATS*4 + 128*4)

__global__ __launch_bounds__(256) void k_mlp(
    const float* __restrict__ x, const float* __restrict__ rnd,
    const float* __restrict__ W1, const float* __restrict__ b1,
    const float* __restrict__ W2, const float* __restrict__ b2,
    float* __restrict__ out)
{
    extern __shared__ float sm[];
    float* sW   = sm;                      // 2 * 64*68
    float* sV   = sW + 2 * WBUF;           // 128*68 = 8704
    float* sB1  = sV + 128 * PITCH;        // 1024
    float* sW2  = sB1 + 1024;              // 3072
    float* sRed = sW2 + 3072;              // 24*128 = 3072
    int*   sIdx = (int*)(sRed + 3072);     // 128

    const int tid = threadIdx.x;
    const int b = blockIdx.y;
    const int j0 = blockIdx.x * 128;

    // W-prefetch lane mapping (4 float4 per thread per 64x64 tile)
    const int w_hl = tid >> 2;              // base row / 4 groups: lin = it*256+tid
    (void)w_hl;
    float4 wreg[4];
    #define LOADW(P) {                                                        \
        _Pragma("unroll")                                                     \
        for (int it = 0; it < 4; ++it) {                                      \
            int lin = it * 256 + tid;                                         \
            int hl = lin >> 4;                                                \
            int c4 = (lin & 15) << 2;                                         \
            wreg[it] = *reinterpret_cast<const float4*>(                      \
                W1 + (((size_t)((P) * 64 + hl)) << 6) + c4);                  \
        } }
    #define STOREW(BUF) {                                                     \
        _Pragma("unroll")                                                     \
        for (int it = 0; it < 4; ++it) {                                      \
            int lin = it * 256 + tid;                                         \
            int hl = lin >> 4;                                                \
            int c4 = (lin & 15) << 2;                                         \
            float2* dd = reinterpret_cast<float2*>(&(BUF)[hl * PITCH + c4]);  \
            dd[0] = make_float2(wreg[it].x, wreg[it].y);                      \
            dd[1] = make_float2(wreg[it].z, wreg[it].w);                      \
        } }

    LOADW(0);   // in flight under the gather

    if (tid < 128) sIdx[tid] = g_sorted[b * NPT + j0 + tid];
    #pragma unroll
    for (int it = 0; it < 4; ++it) sB1[it * 256 + tid] = b1[it * 256 + tid];
    #pragma unroll
    for (int it = 0; it < 12; ++it) sW2[it * 256 + tid] = W2[it * 256 + tid];
    __syncthreads();

    // gather V: [p][c], channels 0..61 from x, 62..63 from rnd
    {
        const int p = tid & 127;
        const int c0 = tid >> 7;          // 0 or 1
        const int gidx = sIdx[p];
        const float* xb = x + (size_t)b * CC * G3 + gidx;
        for (int c = c0; c < CC; c += 2)
            sV[p * PITCH + c] = xb[(size_t)c * G3];
        sV[p * PITCH + 62 + c0] = rnd[((size_t)b * 2 + c0) * NPT + j0 + p] * 2.0f - 1.0f;
    }
    STOREW(sW);        // buffer 0
    __syncthreads();

    const int col = tid & 31;
    const int rowt = tid >> 5;
    float acc0[4] = {0,0,0,0}, acc1[4] = {0,0,0,0}, acc2[4] = {0,0,0,0};

    for (int pass = 0; pass < 16; ++pass) {
        float* cur = sW + (pass & 1) * WBUF;
        float* nxt = sW + ((pass + 1) & 1) * WBUF;
        if (pass < 15) LOADW(pass + 1);   // LDG latency hidden under compute

        u64 s2[8][4];
        #pragma unroll
        for (int i = 0; i < 8; ++i)
            #pragma unroll
            for (int j = 0; j < 4; ++j) s2[i][j] = 0ull;

        #pragma unroll 4
        for (int k2 = 0; k2 < 16; ++k2) {    // 4 k per iter (2 f32x2 pairs)
            ulonglong2 vv[4];
            #pragma unroll
            for (int j = 0; j < 4; ++j)
                vv[j] = *reinterpret_cast<const ulonglong2*>(
                    &sV[(col + 32 * j) * PITCH + (k2 << 2)]);
            #pragma unroll
            for (int i = 0; i < 8; ++i) {
                const ulonglong2 wv = *reinterpret_cast<const ulonglong2*>(
                    &cur[(rowt + 8 * i) * PITCH + (k2 << 2)]);
                #pragma unroll
                for (int j = 0; j < 4; ++j) {
                    s2[i][j] = fma2(wv.x, vv[j].x, s2[i][j]);
                    s2[i][j] = fma2(wv.y, vv[j].y, s2[i][j]);
                }
            }
        }

        // relu + fold into 3 outputs
        #pragma unroll
        for (int i = 0; i < 8; ++i) {
            const int h = pass * 64 + rowt + 8 * i;
            const float bb = sB1[h];
            const float w20 = sW2[h], w21 = sW2[1024 + h], w22 = sW2[2048 + h];
            #pragma unroll
            for (int j = 0; j < 4; ++j) {
                float2 f = *reinterpret_cast<float2*>(&s2[i][j]);
                float s = f.x + f.y + bb;
                s = fmaxf(s, 0.0f);
                acc0[j] = fmaf(w20, s, acc0[j]);
                acc1[j] = fmaf(w21, s, acc1[j]);
                acc2[j] = fmaf(w22, s, acc2[j]);
            }
        }

        if (pass < 15) STOREW(nxt);
        __syncthreads();
    }

    // cross-row reduction (8 partials per point per output)
    #pragma unroll
    for (int j = 0; j < 4; ++j) {
        const int p = col + 32 * j;
        sRed[(rowt * 3 + 0) * 128 + p] = acc0[j];
        sRed[(rowt * 3 + 1) * 128 + p] = acc1[j];
        sRed[(rowt * 3 + 2) * 128 + p] = acc2[j];
    }
    __syncthreads();
    if (tid < 128) {
        const int p = tid;
        float v0 = 0.f, v1 = 0.f, v2 = 0.f;
        #pragma unroll
        for (int r = 0; r < 8; ++r) {
            v0 += sRed[(r * 3 + 0) * 128 + p];
            v1 += sRed[(r * 3 + 1) * 128 + p];
            v2 += sRed[(r * 3 + 2) * 128 + p];
        }
        v0 += __ldg(&b2[0]); v1 += __ldg(&b2[1]); v2 += __ldg(&b2[2]);
        const float nrm = sqrtf(v0 * v0 + v1 * v1 + v2 * v2);
        const float rg = fmaxf(nrm - 0.06661733875264912f, 0.0f);  // sqrt(3)/26
        const int gidx = sIdx[p];
        const int ix = gidx / G2;
        const int rem = gidx - ix * G2;
        const int iy = rem / GG;
        const int iz = rem - iy * GG;
        const float ox = ((float)ix + 0.5f) * 2.0f / 26.0f - 1.0f;
        const float oy = ((float)iy + 0.5f) * 2.0f / 26.0f - 1.0f;
        const float oz = ((float)iz + 0.5f) * 2.0f / 26.0f - 1.0f;
        const size_t j = (size_t)j0 + p;
        out[((size_t)b * 3 + 0) * NPT + j] = v0 + ox;
        out[((size_t)b * 3 + 1) * NPT + j] = v1 + oy;
        out[((size_t)b * 3 + 2) * NPT + j] = v2 + oz;
        out[(size_t)YSZ + (size_t)b * NPT + j] = rg;
    }
}

// ---------------- launch ----------------
extern "C" void kernel_launch(void* const* d_in, const int* in_sizes, int n_in,
                              void* d_out, int out_size) {
    const float* x    = (const float*)d_in[0];
    const float* dens = (const float*)d_in[1];
    const float* rnd  = (const float*)d_in[2];
    const float* u    = (const float*)d_in[3];
    const float* W1   = (const float*)d_in[4];
    const float* b1   = (const float*)d_in[5];
    const float* W2   = (const float*)d_in[6];
    const float* b2   = (const float*)d_in[7];
    float* out = (float*)d_out;

    cudaFuncSetAttribute(k_mlp, cudaFuncAttributeMaxDynamicSharedMemorySize, SMEM_BYTES);

    k_cumsum_rw<<<BB, 1024>>>(dens);
    k_sample<<<(BB * NPT + 255) / 256, 256>>>(u);
    k_scanfill<<<BB, 1024>>>();
    dim3 grid(NPT / 128, BB);
    k_mlp<<<grid, 256, SMEM_BYTES>>>(x, rnd, W1, b1, W2, b2, out);
}

// round 5
// speedup vs baseline: 1.3447x; 1.3447x over previous
#include <cuda_runtime.h>
#include <cstddef>
#include <cstdint>

// Problem constants
#define BB   8
#define CC   62
#define CIN  64
#define GG   26
#define G3   17576          // 26^3
#define G2   676            // 26^2
#define NPT  32768
#define HH   1024
#define YSZ  (BB*3*NPT)     // 786432, offset of reg block in output

typedef unsigned long long u64;

// ---------------- scratch (no allocations allowed) ----------------
__device__ float g_csum[BB * G3];
__device__ int   g_counts[BB * G3];
__device__ int   g_sorted[BB * NPT];

// ---------------- packed f32x2 FMA ----------------
__device__ __forceinline__ u64 fma2(u64 a, u64 b, u64 c) {
    u64 d;
    asm("fma.rn.f32x2 %0, %1, %2, %3;" : "=l"(d) : "l"(a), "l"(b), "l"(c));
    return d;
}

// ---------------- cp.async helpers ----------------
__device__ __forceinline__ void cp_async16(void* smem_dst, const void* gmem_src) {
    uint32_t sa = (uint32_t)__cvta_generic_to_shared(smem_dst);
    asm volatile("cp.async.ca.shared.global [%0], [%1], 16;" :: "r"(sa), "l"(gmem_src));
}
__device__ __forceinline__ void cp_commit() {
    asm volatile("cp.async.commit_group;");
}
__device__ __forceinline__ void cp_wait_all() {
    asm volatile("cp.async.wait_group 0;");
}

// ---------------- kernel 1: XLA:CPU ReduceWindowRewriter-exact cumsum + count zeroing ----------------
#define NB1 1099   // ceil(17576/16)
#define NB2 69     // ceil(1099/16)
#define NB3 5      // ceil(69/16), <= 16 -> naive serial

__global__ __launch_bounds__(1024) void k_cumsum_rw(const float* __restrict__ dens) {
    __shared__ float T1[NB1];
    __shared__ float T2[NB2];
    __shared__ float T3[NB3];
    const int b = blockIdx.x;
    const int tid = threadIdx.x;
    const float* d = dens + (size_t)b * G3;

    // fused: zero this batch's histogram (int4-vectorized, 17576 % 4 == 0)
    {
        int4* cz = reinterpret_cast<int4*>(g_counts + b * G3);
        const int n4 = G3 / 4;  // 4394
        for (int i = tid; i < n4; i += 1024) cz[i] = make_int4(0, 0, 0, 0);
    }

    for (int j = tid; j < NB1; j += 1024) {
        const int s0 = j * 16;
        const int e0 = min(s0 + 16, G3);
        float s = 0.f;
        for (int i = s0; i < e0; ++i) s += d[i];
        T1[j] = s;
    }
    __syncthreads();
    if (tid < NB2) {
        const int s1 = tid * 16;
        const int e1 = min(s1 + 16, NB1);
        float s = 0.f;
        for (int i = s1; i < e1; ++i) s += T1[i];
        T2[tid] = s;
    }
    __syncthreads();
    if (tid == 0) {
        for (int j = 0; j < NB3; ++j) {
            const int s2 = j * 16;
            const int e2 = min(s2 + 16, NB2);
            float s = 0.f;
            for (int i = s2; i < e2; ++i) s += T2[i];
            T3[j] = s;
        }
        float s = 0.f;
        for (int j = 0; j < NB3; ++j) { s += T3[j]; T3[j] = s; }
        for (int j2 = 0; j2 < NB3; ++j2) {
            const float P = (j2 > 0) ? T3[j2 - 1] : 0.0f;
            float sr = 0.f;
            const int s2 = j2 * 16, e2 = min(j2 * 16 + 16, NB2);
            for (int i = s2; i < e2; ++i) {
                sr += T2[i];
                T2[i] = sr + P;
            }
        }
    }
    __syncthreads();
    if (tid < NB2) {
        const float P = (tid > 0) ? T2[tid - 1] : 0.0f;
        float sr = 0.f;
        const int s1 = tid * 16, e1 = min(tid * 16 + 16, NB1);
        for (int i = s1; i < e1; ++i) {
            sr += T1[i];
            T1[i] = sr + P;
        }
    }
    __syncthreads();
    float* cs = g_csum + (size_t)b * G3;
    for (int j = tid; j < NB1; j += 1024) {
        const float P = (j > 0) ? T1[j - 1] : 0.0f;
        float sr = 0.f;
        const int s0 = j * 16, e0 = min(j * 16 + 16, G3);
        for (int i = s0; i < e0; ++i) {
            sr += d[i];
            cs[i] = sr + P;
        }
    }
}

// ---------------- kernel 2: sample -> histogram ----------------
__global__ void k_sample(const float* __restrict__ u) {
    int g = blockIdx.x * blockDim.x + threadIdx.x;
    if (g >= BB * NPT) return;
    int b = g >> 15;
    const float* cs = g_csum + (size_t)b * G3;
    float total = cs[G3 - 1];
    float t = u[g] * total;
    int lo = 0, hi = G3;
    while (lo < hi) {
        int mid = (lo + hi) >> 1;
        if (cs[mid] <= t) lo = mid + 1; else hi = mid;
    }
    int idx = lo;
    if (idx > G3 - 1) idx = G3 - 1;
    atomicAdd(&g_counts[b * G3 + idx], 1);
}

// ---------------- kernel 3: single-pass counting-sort emit ----------------
#define BINS_PT 18
__global__ __launch_bounds__(1024) void k_scanfill() {
    const int b = blockIdx.x;
    const int* cnt = g_counts + b * G3;
    int* srt = g_sorted + b * NPT;

    __shared__ int wsum[32];
    const int tid = threadIdx.x;
    const int lane = tid & 31, wid = tid >> 5;
    const int base = tid * BINS_PT;

    int c[BINS_PT];
    int pre[BINS_PT];
    int s = 0;
    #pragma unroll
    for (int r = 0; r < BINS_PT; ++r) {
        const int i = base + r;
        c[r] = (i < G3) ? cnt[i] : 0;
        pre[r] = s;
        s += c[r];
    }
    int x = s;
    #pragma unroll
    for (int d = 1; d < 32; d <<= 1) {
        int y = __shfl_up_sync(0xffffffffu, x, d);
        if (lane >= d) x += y;
    }
    if (lane == 31) wsum[wid] = x;
    __syncthreads();
    if (wid == 0) {
        int t = wsum[lane];
        #pragma unroll
        for (int d = 1; d < 32; d <<= 1) {
            int y = __shfl_up_sync(0xffffffffu, t, d);
            if (lane >= d) t += y;
        }
        wsum[lane] = t;
    }
    __syncthreads();
    const int excl = (x - s) + (wid ? wsum[wid - 1] : 0);

    #pragma unroll
    for (int r = 0; r < BINS_PT; ++r) {
        const int i = base + r;
        const int o = excl + pre[r];
        for (int k = 0; k < c[r]; ++k) srt[o + k] = i;
    }
}

// ---------------- kernel 4: fused gather + MLP + epilogue ----------------
// Block: 256 threads, 128 points, 16 passes of 64 h-rows.
// Thread tile: 8 h x 4 points, f32x2 packed over k-pairs.
// W1 tiles double-buffered via cp.async (no register payload), 1 sync/pass.
#define PITCH 68
#define WBUF  (64 * PITCH)
#define SMEM_FLOATS (2*WBUF + 128*PITCH + 1024 + 3072 + 3072)
#define SMEM_BYTES  (SMEM_FLOATS*4 + 128*4)

__global__ __launch_bounds__(256, 2) void k_mlp(
    const float* __restrict__ x, const float* __restrict__ rnd,
    const float* __restrict__ W1, const float* __restrict__ b1,
    const float* __restrict__ W2, const float* __restrict__ b2,
    float* __restrict__ out)
{
    extern __shared__ float sm[];
    float* sW   = sm;                      // 2 * 64*68
    float* sV   = sW + 2 * WBUF;           // 128*68 = 8704
    float* sB1  = sV + 128 * PITCH;        // 1024
    float* sW2  = sB1 + 1024;              // 3072
    float* sRed = sW2 + 3072;              // 24*128 = 3072
    int*   sIdx = (int*)(sRed + 3072);     // 128

    const int tid = threadIdx.x;
    const int b = blockIdx.y;
    const int j0 = blockIdx.x * 128;

    // cp.async W1 tile loader: 4 x 16B per thread per 64x64 tile (pitch-68 dst)
    #define LOADW_ASYNC(P, BUF) {                                             \
        _Pragma("unroll")                                                     \
        for (int it = 0; it < 4; ++it) {                                      \
            int lin = it * 256 + tid;                                         \
            int hl = lin >> 4;                                                \
            int c4 = (lin & 15) << 2;                                         \
            cp_async16(&(BUF)[hl * PITCH + c4],                               \
                       W1 + (((size_t)((P) * 64 + hl)) << 6) + c4);           \
        }                                                                     \
        cp_commit(); }

    LOADW_ASYNC(0, sW);    // in flight under the gather

    if (tid < 128) sIdx[tid] = g_sorted[b * NPT + j0 + tid];
    #pragma unroll
    for (int it = 0; it < 4; ++it) sB1[it * 256 + tid] = b1[it * 256 + tid];
    #pragma unroll
    for (int it = 0; it < 12; ++it) sW2[it * 256 + tid] = W2[it * 256 + tid];
    __syncthreads();

    // gather V: [p][c], channels 0..61 from x, 62..63 from rnd
    {
        const int p = tid & 127;
        const int c0 = tid >> 7;          // 0 or 1
        const int gidx = sIdx[p];
        const float* xb = x + (size_t)b * CC * G3 + gidx;
        for (int c = c0; c < CC; c += 2)
            sV[p * PITCH + c] = xb[(size_t)c * G3];
        sV[p * PITCH + 62 + c0] = rnd[((size_t)b * 2 + c0) * NPT + j0 + p] * 2.0f - 1.0f;
    }
    cp_wait_all();
    __syncthreads();

    const int col = tid & 31;
    const int rowt = tid >> 5;
    float acc0[4] = {0,0,0,0}, acc1[4] = {0,0,0,0}, acc2[4] = {0,0,0,0};

    for (int pass = 0; pass < 16; ++pass) {
        float* cur = sW + (pass & 1) * WBUF;
        float* nxt = sW + ((pass + 1) & 1) * WBUF;
        if (pass < 15) LOADW_ASYNC(pass + 1, nxt);   // latency hidden under compute

        u64 s2[8][4];
        #pragma unroll
        for (int i = 0; i < 8; ++i)
            #pragma unroll
            for (int j = 0; j < 4; ++j) s2[i][j] = 0ull;

        #pragma unroll 4
        for (int k2 = 0; k2 < 16; ++k2) {    // 4 k per iter (2 f32x2 pairs)
            ulonglong2 vv[4];
            #pragma unroll
            for (int j = 0; j < 4; ++j)
                vv[j] = *reinterpret_cast<const ulonglong2*>(
                    &sV[(col + 32 * j) * PITCH + (k2 << 2)]);
            #pragma unroll
            for (int i = 0; i < 8; ++i) {
                const ulonglong2 wv = *reinterpret_cast<const ulonglong2*>(
                    &cur[(rowt + 8 * i) * PITCH + (k2 << 2)]);
                #pragma unroll
                for (int j = 0; j < 4; ++j) {
                    s2[i][j] = fma2(wv.x, vv[j].x, s2[i][j]);
                    s2[i][j] = fma2(wv.y, vv[j].y, s2[i][j]);
                }
            }
        }

        // relu + fold into 3 outputs
        #pragma unroll
        for (int i = 0; i < 8; ++i) {
            const int h = pass * 64 + rowt + 8 * i;
            const float bb = sB1[h];
            const float w20 = sW2[h], w21 = sW2[1024 + h], w22 = sW2[2048 + h];
            #pragma unroll
            for (int j = 0; j < 4; ++j) {
                float2 f = *reinterpret_cast<float2*>(&s2[i][j]);
                float s = f.x + f.y + bb;
                s = fmaxf(s, 0.0f);
                acc0[j] = fmaf(w20, s, acc0[j]);
                acc1[j] = fmaf(w21, s, acc1[j]);
                acc2[j] = fmaf(w22, s, acc2[j]);
            }
        }

        if (pass < 15) cp_wait_all();
        __syncthreads();
    }

    // cross-row reduction (8 partials per point per output)
    #pragma unroll
    for (int j = 0; j < 4; ++j) {
        const int p = col + 32 * j;
        sRed[(rowt * 3 + 0) * 128 + p] = acc0[j];
        sRed[(rowt * 3 + 1) * 128 + p] = acc1[j];
        sRed[(rowt * 3 + 2) * 128 + p] = acc2[j];
    }
    __syncthreads();
    if (tid < 128) {
        const int p = tid;
        float v0 = 0.f, v1 = 0.f, v2 = 0.f;
        #pragma unroll
        for (int r = 0; r < 8; ++r) {
            v0 += sRed[(r * 3 + 0) * 128 + p];
            v1 += sRed[(r * 3 + 1) * 128 + p];
            v2 += sRed[(r * 3 + 2) * 128 + p];
        }
        v0 += __ldg(&b2[0]); v1 += __ldg(&b2[1]); v2 += __ldg(&b2[2]);
        const float nrm = sqrtf(v0 * v0 + v1 * v1 + v2 * v2);
        const float rg = fmaxf(nrm - 0.06661733875264912f, 0.0f);  // sqrt(3)/26
        const int gidx = sIdx[p];
        const int ix = gidx / G2;
        const int rem = gidx - ix * G2;
        const int iy = rem / GG;
        const int iz = rem - iy * GG;
        const float ox = ((float)ix + 0.5f) * 2.0f / 26.0f - 1.0f;
        const float oy = ((float)iy + 0.5f) * 2.0f / 26.0f - 1.0f;
        const float oz = ((float)iz + 0.5f) * 2.0f / 26.0f - 1.0f;
        const size_t j = (size_t)j0 + p;
        out[((size_t)b * 3 + 0) * NPT + j] = v0 + ox;
        out[((size_t)b * 3 + 1) * NPT + j] = v1 + oy;
        out[((size_t)b * 3 + 2) * NPT + j] = v2 + oz;
        out[(size_t)YSZ + (size_t)b * NPT + j] = rg;
    }
}

// ---------------- launch ----------------
extern "C" void kernel_launch(void* const* d_in, const int* in_sizes, int n_in,
                              void* d_out, int out_size) {
    const float* x    = (const float*)d_in[0];
    const float* dens = (const float*)d_in[1];
    const float* rnd  = (const float*)d_in[2];
    const float* u    = (const float*)d_in[3];
    const float* W1   = (const float*)d_in[4];
    const float* b1   = (const float*)d_in[5];
    const float* W2   = (const float*)d_in[6];
    const float* b2   = (const float*)d_in[7];
    float* out = (float*)d_out;

    cudaFuncSetAttribute(k_mlp, cudaFuncAttributeMaxDynamicSharedMemorySize, SMEM_BYTES);

    k_cumsum_rw<<<BB, 1024>>>(dens);
    k_sample<<<(BB * NPT + 255) / 256, 256>>>(u);
    k_scanfill<<<BB, 1024>>>();
    dim3 grid(NPT / 128, BB);
    k_mlp<<<grid, 256, SMEM_BYTES>>>(x, rnd, W1, b1, W2, b2, out);
}

// round 7
// speedup vs baseline: 2.8643x; 2.1300x over previous
#include <cuda_runtime.h>
#include <cuda_bf16.h>
#include <cstdint>
#include <cstddef>

// Problem constants
#define BB   8
#define CC   62
#define GG   26
#define G3   17576
#define G2   676
#define NPT  32768
#define HH   1024
#define YSZ  (BB*3*NPT)

// ---------------- scratch ----------------
__device__ float g_csum[BB * G3];
__device__ int   g_counts[BB * G3];
__device__ int   g_sorted[BB * NPT];
__device__ __align__(16) __nv_bfloat16 g_w1hi[HH * 64];
__device__ __align__(16) __nv_bfloat16 g_w1lo[HH * 64];
__device__ float4 g_pack[HH];   // (b1, w2_0, w2_1, w2_2)

// ---------------- PTX helpers ----------------
__device__ __forceinline__ uint32_t smem_u32(const void* p) {
    uint32_t a;
    asm("{ .reg .u64 t; cvta.to.shared.u64 t, %1; cvt.u32.u64 %0, t; }" : "=r"(a) : "l"(p));
    return a;
}
__device__ __forceinline__ void cp_async16(uint32_t smem_dst, const void* gmem_src) {
    asm volatile("cp.async.ca.shared.global [%0], [%1], 16;" :: "r"(smem_dst), "l"(gmem_src));
}
__device__ __forceinline__ void cp_commit() { asm volatile("cp.async.commit_group;"); }
template <int N>
__device__ __forceinline__ void cp_wait() { asm volatile("cp.async.wait_group %0;" :: "n"(N)); }

__device__ __forceinline__ void ldsm_x4(uint32_t* r, uint32_t addr) {
    asm volatile("ldmatrix.sync.aligned.m8n8.x4.shared.b16 {%0,%1,%2,%3}, [%4];"
                 : "=r"(r[0]), "=r"(r[1]), "=r"(r[2]), "=r"(r[3]) : "r"(addr));
}
__device__ __forceinline__ void mma16816(float* d, const uint32_t* a, const uint32_t* b) {
    asm volatile(
        "mma.sync.aligned.m16n8k16.row.col.f32.bf16.bf16.f32 "
        "{%0,%1,%2,%3}, {%4,%5,%6,%7}, {%8,%9}, {%0,%1,%2,%3};"
        : "+f"(d[0]), "+f"(d[1]), "+f"(d[2]), "+f"(d[3])
        : "r"(a[0]), "r"(a[1]), "r"(a[2]), "r"(a[3]), "r"(b[0]), "r"(b[1]));
}

// ---------------- kernel: prep W1 split + pack ----------------
__global__ void k_prepw(const float* __restrict__ W1, const float* __restrict__ b1,
                        const float* __restrict__ W2) {
    int i = blockIdx.x * blockDim.x + threadIdx.x;
    if (i < HH * 64) {
        float w = W1[i];
        __nv_bfloat16 hi = __float2bfloat16(w);
        __nv_bfloat16 lo = __float2bfloat16(w - __bfloat162float(hi));
        g_w1hi[i] = hi;
        g_w1lo[i] = lo;
    }
    if (i < HH) g_pack[i] = make_float4(b1[i], W2[i], W2[HH + i], W2[2 * HH + i]);
}

// ---------------- kernel 1: XLA:CPU ReduceWindowRewriter-exact cumsum + zero counts ----------------
#define NB1 1099
#define NB2 69
#define NB3 5
__global__ __launch_bounds__(1024) void k_cumsum_rw(const float* __restrict__ dens) {
    __shared__ float T1[NB1];
    __shared__ float T2[NB2];
    __shared__ float T3[NB3];
    const int b = blockIdx.x;
    const int tid = threadIdx.x;
    const float* d = dens + (size_t)b * G3;

    {
        int4* cz = reinterpret_cast<int4*>(g_counts + b * G3);
        for (int i = tid; i < G3 / 4; i += 1024) cz[i] = make_int4(0, 0, 0, 0);
    }
    for (int j = tid; j < NB1; j += 1024) {
        const int s0 = j * 16, e0 = min(s0 + 16, G3);
        float s = 0.f;
        for (int i = s0; i < e0; ++i) s += d[i];
        T1[j] = s;
    }
    __syncthreads();
    if (tid < NB2) {
        const int s1 = tid * 16, e1 = min(s1 + 16, NB1);
        float s = 0.f;
        for (int i = s1; i < e1; ++i) s += T1[i];
        T2[tid] = s;
    }
    __syncthreads();
    if (tid == 0) {
        for (int j = 0; j < NB3; ++j) {
            const int s2 = j * 16, e2 = min(s2 + 16, NB2);
            float s = 0.f;
            for (int i = s2; i < e2; ++i) s += T2[i];
            T3[j] = s;
        }
        float s = 0.f;
        for (int j = 0; j < NB3; ++j) { s += T3[j]; T3[j] = s; }
        for (int j2 = 0; j2 < NB3; ++j2) {
            const float P = (j2 > 0) ? T3[j2 - 1] : 0.0f;
            float sr = 0.f;
            const int s2 = j2 * 16, e2 = min(j2 * 16 + 16, NB2);
            for (int i = s2; i < e2; ++i) { sr += T2[i]; T2[i] = sr + P; }
        }
    }
    __syncthreads();
    if (tid < NB2) {
        const float P = (tid > 0) ? T2[tid - 1] : 0.0f;
        float sr = 0.f;
        const int s1 = tid * 16, e1 = min(tid * 16 + 16, NB1);
        for (int i = s1; i < e1; ++i) { sr += T1[i]; T1[i] = sr + P; }
    }
    __syncthreads();
    float* cs = g_csum + (size_t)b * G3;
    for (int j = tid; j < NB1; j += 1024) {
        const float P = (j > 0) ? T1[j - 1] : 0.0f;
        float sr = 0.f;
        const int s0 = j * 16, e0 = min(j * 16 + 16, G3);
        for (int i = s0; i < e0; ++i) { sr += d[i]; cs[i] = sr + P; }
    }
}

// ---------------- kernel 2: sample -> histogram ----------------
__global__ void k_sample(const float* __restrict__ u) {
    int g = blockIdx.x * blockDim.x + threadIdx.x;
    if (g >= BB * NPT) return;
    int b = g >> 15;
    const float* cs = g_csum + (size_t)b * G3;
    float t = u[g] * cs[G3 - 1];
    int lo = 0, hi = G3;
    while (lo < hi) {
        int mid = (lo + hi) >> 1;
        if (cs[mid] <= t) lo = mid + 1; else hi = mid;
    }
    if (lo > G3 - 1) lo = G3 - 1;
    atomicAdd(&g_counts[b * G3 + lo], 1);
}

// ---------------- kernel 3: single-pass counting-sort emit ----------------
#define BINS_PT 18
__global__ __launch_bounds__(1024) void k_scanfill() {
    const int b = blockIdx.x;
    const int* cnt = g_counts + b * G3;
    int* srt = g_sorted + b * NPT;
    __shared__ int wsum[32];
    const int tid = threadIdx.x;
    const int lane = tid & 31, wid = tid >> 5;
    const int base = tid * BINS_PT;

    int c[BINS_PT], pre[BINS_PT];
    int s = 0;
    #pragma unroll
    for (int r = 0; r < BINS_PT; ++r) {
        const int i = base + r;
        c[r] = (i < G3) ? cnt[i] : 0;
        pre[r] = s; s += c[r];
    }
    int x = s;
    #pragma unroll
    for (int d = 1; d < 32; d <<= 1) {
        int y = __shfl_up_sync(0xffffffffu, x, d);
        if (lane >= d) x += y;
    }
    if (lane == 31) wsum[wid] = x;
    __syncthreads();
    if (wid == 0) {
        int t = wsum[lane];
        #pragma unroll
        for (int d = 1; d < 32; d <<= 1) {
            int y = __shfl_up_sync(0xffffffffu, t, d);
            if (lane >= d) t += y;
        }
        wsum[lane] = t;
    }
    __syncthreads();
    const int excl = (x - s) + (wid ? wsum[wid - 1] : 0);
    #pragma unroll
    for (int r = 0; r < BINS_PT; ++r) {
        const int o = excl + pre[r];
        for (int k = 0; k < c[r]; ++k) srt[o + k] = base + r;
    }
}

// ---------------- kernel 4: HMMA (mma.sync bf16) fused MLP ----------------
// 512 threads / 16 warps / 256 points per CTA. Warp w owns points [w*16, w*16+16)
// across all 1024 h. V hi/lo in smem pitch-144B; W1 hi/lo streamed in 128-h
// chunks (cp.async double buffer). 3 products emulate fp32.
#define VPITCHB 144                      // 72 bf16 per row
#define SM_VHI  0
#define SM_VLO  36864                    // 256*144
#define SM_W    73728                    // 2 bufs x 36864 (hi 18432 + lo 18432)
#define WHALF   18432                    // 128*144
#define WBUFSZ  36864
#define SM_PACK 147456                   // 1024 float4 = 16384
#define SM_IDX  163840                   // 256 ints
#define SM_TOTAL (SM_IDX + 1024 + 64)

__global__ __launch_bounds__(512, 1) void k_mlp_mma(
    const float* __restrict__ x, const float* __restrict__ rnd,
    const float* __restrict__ b2, float* __restrict__ out)
{
    extern __shared__ char smem[];
    const uint32_t sbase = smem_u32(smem);
    const int tid = threadIdx.x;
    const int wid = tid >> 5;
    const int lane = tid & 31;
    const int b = blockIdx.y;
    const int j0 = blockIdx.x * 256;

    int* sIdx = (int*)(smem + SM_IDX);
    const float4* sPack = (const float4*)(smem + SM_PACK);
    float4* sPackW = (float4*)(smem + SM_PACK);

    // kick W chunk 0 and 1 (cp.async). 2048 x 16B per chunk / 512 thr = 4 each.
    #define KICKW(CH, BUFI) {                                                   \
        _Pragma("unroll")                                                       \
        for (int i = 0; i < 4; ++i) {                                           \
            int lin = i * 512 + tid;                                            \
            int m = lin >> 10;                                                  \
            int r = (lin >> 3) & 127;                                           \
            int sg = lin & 7;                                                   \
            const __nv_bfloat16* src =                                          \
                (m ? g_w1lo : g_w1hi) + ((CH) * 128 + r) * 64 + sg * 8;         \
            cp_async16(sbase + SM_W + (BUFI) * WBUFSZ + m * WHALF               \
                       + r * VPITCHB + sg * 16, src);                           \
        }                                                                       \
        cp_commit(); }

    KICKW(0, 0);
    KICKW(1, 1);

    if (tid < 256) sIdx[tid] = g_sorted[b * NPT + j0 + tid];
    sPackW[tid] = g_pack[tid];
    sPackW[tid + 512] = g_pack[tid + 512];
    __syncthreads();

    // gather V -> bf16 hi/lo smem tiles (2 threads per point)
    {
        const int p = tid & 255;
        const int c0 = tid >> 8;
        const int gidx = sIdx[p];
        const float* xb = x + (size_t)b * CC * G3 + gidx;
        __nv_bfloat16* vhi = (__nv_bfloat16*)(smem + SM_VHI);
        __nv_bfloat16* vlo = (__nv_bfloat16*)(smem + SM_VLO);
        for (int c = c0; c < CC; c += 2) {
            float v = xb[(size_t)c * G3];
            __nv_bfloat16 hi = __float2bfloat16(v);
            __nv_bfloat16 lo = __float2bfloat16(v - __bfloat162float(hi));
            vhi[p * 72 + c] = hi;
            vlo[p * 72 + c] = lo;
        }
        {
            float v = rnd[((size_t)b * 2 + c0) * NPT + j0 + p] * 2.0f - 1.0f;
            __nv_bfloat16 hi = __float2bfloat16(v);
            __nv_bfloat16 lo = __float2bfloat16(v - __bfloat162float(hi));
            vhi[p * 72 + 62 + c0] = hi;
            vlo[p * 72 + 62 + c0] = lo;
        }
    }
    cp_wait<1>();        // chunk 0 resident
    __syncthreads();

    // A fragments (16 pts x 64 k, hi & lo), loaded once via ldmatrix.x4
    uint32_t ahi[4][4], alo[4][4];
    {
        const uint32_t rowoff = (uint32_t)((wid * 16 + (lane & 15)) * VPITCHB
                                           + ((lane >> 4) << 4));
        #pragma unroll
        for (int ks = 0; ks < 4; ++ks) {
            ldsm_x4(ahi[ks], sbase + SM_VHI + rowoff + ks * 32);
            ldsm_x4(alo[ks], sbase + SM_VLO + rowoff + ks * 32);
        }
    }

    float accA0 = 0.f, accA1 = 0.f, accA2 = 0.f;   // row r
    float accB0 = 0.f, accB1 = 0.f, accB2 = 0.f;   // row r+8

    for (int ch = 0; ch < 8; ++ch) {
        const uint32_t wbuf = sbase + SM_W + (ch & 1) * WBUFSZ;
        const uint32_t bladdr = (uint32_t)(((lane & 7) * VPITCHB) + ((lane >> 3) << 4));

        #pragma unroll 2
        for (int t8 = 0; t8 < 16; ++t8) {
            uint32_t bh[8], bl[8];
            const uint32_t ba = wbuf + t8 * 8 * VPITCHB + bladdr;
            ldsm_x4(&bh[0], ba);
            ldsm_x4(&bh[4], ba + 64);
            ldsm_x4(&bl[0], ba + WHALF);
            ldsm_x4(&bl[4], ba + WHALF + 64);

            float dhh[4] = {0.f, 0.f, 0.f, 0.f};
            float dhl[4] = {0.f, 0.f, 0.f, 0.f};
            float dlh[4] = {0.f, 0.f, 0.f, 0.f};
            #pragma unroll
            for (int ks = 0; ks < 4; ++ks) {
                mma16816(dhh, ahi[ks], &bh[ks * 2]);
                mma16816(dhl, ahi[ks], &bl[ks * 2]);
                mma16816(dlh, alo[ks], &bh[ks * 2]);
            }

            const int h0 = ch * 128 + t8 * 8 + ((lane & 3) << 1);
            const float4 pk0 = sPack[h0];
            const float4 pk1 = sPack[h0 + 1];
            float d0 = dhh[0] + dhl[0] + dlh[0];
            float d1 = dhh[1] + dhl[1] + dlh[1];
            float d2 = dhh[2] + dhl[2] + dlh[2];
            float d3 = dhh[3] + dhl[3] + dlh[3];
            float s0 = fmaxf(d0 + pk0.x, 0.f);
            float s1 = fmaxf(d1 + pk1.x, 0.f);
            float s2 = fmaxf(d2 + pk0.x, 0.f);
            float s3 = fmaxf(d3 + pk1.x, 0.f);
            accA0 = fmaf(pk0.y, s0, accA0); accA0 = fmaf(pk1.y, s1, accA0);
            accA1 = fmaf(pk0.z, s0, accA1); accA1 = fmaf(pk1.z, s1, accA1);
            accA2 = fmaf(pk0.w, s0, accA2); accA2 = fmaf(pk1.w, s1, accA2);
            accB0 = fmaf(pk0.y, s2, accB0); accB0 = fmaf(pk1.y, s3, accB0);
            accB1 = fmaf(pk0.z, s2, accB1); accB1 = fmaf(pk1.z, s3, accB1);
            accB2 = fmaf(pk0.w, s2, accB2); accB2 = fmaf(pk1.w, s3, accB2);
        }

        __syncthreads();     // all warps done reading buf (ch&1)
        if (ch < 6) {
            KICKW(ch + 2, ch & 1);
            cp_wait<1>();    // chunk ch+1 resident
        } else if (ch == 6) {
            cp_wait<0>();    // chunk 7 resident
        }
        __syncthreads();
    }

    // quad reduce (lanes sharing the same D rows)
    #pragma unroll
    for (int d = 1; d < 4; d <<= 1) {
        accA0 += __shfl_xor_sync(0xffffffffu, accA0, d);
        accA1 += __shfl_xor_sync(0xffffffffu, accA1, d);
        accA2 += __shfl_xor_sync(0xffffffffu, accA2, d);
        accB0 += __shfl_xor_sync(0xffffffffu, accB0, d);
        accB1 += __shfl_xor_sync(0xffffffffu, accB1, d);
        accB2 += __shfl_xor_sync(0xffffffffu, accB2, d);
    }

    if ((lane & 3) == 0) {
        const float bb0 = __ldg(&b2[0]);
        const float bb1 = __ldg(&b2[1]);
        const float bb2 = __ldg(&b2[2]);
        #pragma unroll
        for (int half = 0; half < 2; ++half) {
            const int p = wid * 16 + (lane >> 2) + half * 8;
            float v0 = (half ? accB0 : accA0) + bb0;
            float v1 = (half ? accB1 : accA1) + bb1;
            float v2 = (half ? accB2 : accA2) + bb2;
            const float nrm = sqrtf(v0 * v0 + v1 * v1 + v2 * v2);
            const float rg = fmaxf(nrm - 0.06661733875264912f, 0.0f);
            const int gidx = sIdx[p];
            const int ix = gidx / G2;
            const int rem = gidx - ix * G2;
            const int iy = rem / GG;
            const int iz = rem - iy * GG;
            const float ox = ((float)ix + 0.5f) * 2.0f / 26.0f - 1.0f;
            const float oy = ((float)iy + 0.5f) * 2.0f / 26.0f - 1.0f;
            const float oz = ((float)iz + 0.5f) * 2.0f / 26.0f - 1.0f;
            const size_t j = (size_t)j0 + p;
            out[((size_t)b * 3 + 0) * NPT + j] = v0 + ox;
            out[((size_t)b * 3 + 1) * NPT + j] = v1 + oy;
            out[((size_t)b * 3 + 2) * NPT + j] = v2 + oz;
            out[(size_t)YSZ + (size_t)b * NPT + j] = rg;
        }
    }
}

// ---------------- launch ----------------
extern "C" void kernel_launch(void* const* d_in, const int* in_sizes, int n_in,
                              void* d_out, int out_size) {
    const float* x    = (const float*)d_in[0];
    const float* dens = (const float*)d_in[1];
    const float* rnd  = (const float*)d_in[2];
    const float* u    = (const float*)d_in[3];
    const float* W1   = (const float*)d_in[4];
    const float* b1   = (const float*)d_in[5];
    const float* W2   = (const float*)d_in[6];
    const float* b2   = (const float*)d_in[7];
    float* out = (float*)d_out;

    cudaFuncSetAttribute(k_mlp_mma, cudaFuncAttributeMaxDynamicSharedMemorySize, SM_TOTAL);

    k_prepw<<<(HH * 64 + 255) / 256, 256>>>(W1, b1, W2);
    k_cumsum_rw<<<BB, 1024>>>(dens);
    k_sample<<<(BB * NPT + 255) / 256, 256>>>(u);
    k_scanfill<<<BB, 1024>>>();
    dim3 grid(NPT / 256, BB);
    k_mlp_mma<<<grid, 512, SM_TOTAL>>>(x, rnd, b2, out);
}